// round 3
// baseline (speedup 1.0000x reference)
#include <cuda_runtime.h>

#define HID 32

static const int MAXN = 100000;
static const int MAXE = 3200000;
static const int MAXG = 512;

// ---------------- device scratch (no allocations; referenced only by symbol) ----
__device__ int   g_deg[MAXN];
__device__ int   g_rowptr[MAXN + 1];
__device__ int   g_cursor[MAXN];
__device__ float g_dinv[MAXN];
__device__ int   g_csr_src[MAXE];
__device__ __align__(16) float g_bufA[(size_t)MAXN * HID];
__device__ __align__(16) float g_bufB[(size_t)MAXN * HID];
__device__ __align__(16) float g_sums[MAXG * HID];
__device__ int   g_cnt[MAXG];

// ---------------- zero scratch that must start at 0 each call ----------------
__global__ void k_zero(int n_nodes, int n_graphs) {
    int i = blockIdx.x * blockDim.x + threadIdx.x;
    int stride = gridDim.x * blockDim.x;
    for (int k = i; k < n_nodes; k += stride) g_deg[k] = 0;
    for (int k = i; k < n_graphs * HID; k += stride) g_sums[k] = 0.0f;
    for (int k = i; k < n_graphs; k += stride) g_cnt[k] = 0;
}

// ---------------- degree histogram over dst (edge_index is int32) ----------------
__global__ void k_deg(const int* __restrict__ ei, int n_edges) {
    int i = blockIdx.x * blockDim.x + threadIdx.x;
    int stride = gridDim.x * blockDim.x;
    for (int e = i; e < n_edges; e += stride) {
        int d = ei[n_edges + e];
        atomicAdd(&g_deg[d], 1);
    }
}

// ---------------- single-block exclusive scan -> rowptr, cursor, dinv ----------------
__global__ void k_scan(int n) {
    __shared__ int part[1024];
    int t = threadIdx.x;
    int chunk = (n + 1023) >> 10;
    int beg = min(t * chunk, n);
    int end = min(beg + chunk, n);
    int s = 0;
    for (int i = beg; i < end; i++) s += g_deg[i];
    part[t] = s;
    __syncthreads();
    // Hillis-Steele inclusive scan over 1024 partials
    for (int off = 1; off < 1024; off <<= 1) {
        int v = (t >= off) ? part[t - off] : 0;
        __syncthreads();
        part[t] += v;
        __syncthreads();
    }
    int run = (t == 0) ? 0 : part[t - 1];
    for (int i = beg; i < end; i++) {
        g_rowptr[i] = run;
        g_cursor[i] = run;
        g_dinv[i] = rsqrtf((float)g_deg[i] + 1.0f);
        run += g_deg[i];
    }
    if (t == 1023) g_rowptr[n] = part[1023];
}

// ---------------- CSR fill: csr_src grouped by dst ----------------
__global__ void k_fill(const int* __restrict__ ei, int n_edges) {
    int i = blockIdx.x * blockDim.x + threadIdx.x;
    int stride = gridDim.x * blockDim.x;
    for (int e = i; e < n_edges; e += stride) {
        int s = ei[e];
        int d = ei[n_edges + e];
        int pos = atomicAdd(&g_cursor[d], 1);
        g_csr_src[pos] = s;
    }
}

// ---------------- dense GEMM: Y[n,32] = X[n,K] @ W[K,32] ----------------
// IN_EXT: read X from the external pointer; otherwise read g_bufB.
// Output always goes to g_bufA.
template <int K, bool IN_EXT>
__global__ void k_gemm(const float* __restrict__ Xext, const float* __restrict__ W,
                       int n) {
    __shared__ float Ws[K * HID];
    for (int i = threadIdx.x; i < K * HID; i += blockDim.x) Ws[i] = W[i];
    __syncthreads();

    int node = blockIdx.x * blockDim.x + threadIdx.x;
    if (node >= n) return;

    const float* X = IN_EXT ? Xext : (const float*)g_bufB;

    float4 acc[8];
#pragma unroll
    for (int j = 0; j < 8; j++) acc[j] = make_float4(0.f, 0.f, 0.f, 0.f);

    const float4* xp = (const float4*)(X + (size_t)node * K);
#pragma unroll 4
    for (int k4 = 0; k4 < K / 4; k4++) {
        float4 xv = __ldg(xp + k4);
        float xs[4] = {xv.x, xv.y, xv.z, xv.w};
#pragma unroll
        for (int kk = 0; kk < 4; kk++) {
            float xk = xs[kk];
            const float4* wr = (const float4*)&Ws[(k4 * 4 + kk) * HID];
#pragma unroll
            for (int j = 0; j < 8; j++) {
                float4 w = wr[j];
                acc[j].x += xk * w.x;
                acc[j].y += xk * w.y;
                acc[j].z += xk * w.z;
                acc[j].w += xk * w.w;
            }
        }
    }
    float4* yp = (float4*)(g_bufA + (size_t)node * HID);
#pragma unroll
    for (int j = 0; j < 8; j++) yp[j] = acc[j];
}

// ---------------- pull aggregation (register accumulators, no atomics) ----------------
// Reads g_bufA, writes g_bufB.
// out = relu( dinv_d * (sum_s dinv_s*h_s + dinv_d*h_d) + b )
// 8 threads per node; each thread owns one float4 column slot.
__global__ void k_pull(const float* __restrict__ bias, int n) {
    int gid = blockIdx.x * blockDim.x + threadIdx.x;
    int node = gid >> 3;
    int l8 = gid & 7;
    if (node >= n) return;

    float dv = g_dinv[node];
    const float4* hp = (const float4*)g_bufA;
    float4 hd = __ldg(&hp[(size_t)node * 8 + l8]);
    float4 acc = make_float4(hd.x * dv, hd.y * dv, hd.z * dv, hd.w * dv);

    int beg = g_rowptr[node], end = g_rowptr[node + 1];
    for (int e = beg; e < end; e++) {
        int s = g_csr_src[e];
        float ds = __ldg(&g_dinv[s]);
        float4 v = __ldg(&hp[(size_t)s * 8 + l8]);
        acc.x += ds * v.x;
        acc.y += ds * v.y;
        acc.z += ds * v.z;
        acc.w += ds * v.w;
    }
    float4 b = __ldg(&((const float4*)bias)[l8]);
    acc.x = fmaxf(acc.x * dv + b.x, 0.0f);
    acc.y = fmaxf(acc.y * dv + b.y, 0.0f);
    acc.z = fmaxf(acc.z * dv + b.z, 0.0f);
    acc.w = fmaxf(acc.w * dv + b.w, 0.0f);
    ((float4*)g_bufB)[(size_t)node * 8 + l8] = acc;
}

// ---------------- pull + fused mean-pool accumulation (reads g_bufA) ----------------
__global__ void k_pull_pool(const float* __restrict__ bias,
                            const int* __restrict__ batch, int n) {
    int gid = blockIdx.x * blockDim.x + threadIdx.x;
    int node = gid >> 3;
    int l8 = gid & 7;
    if (node >= n) return;

    float dv = g_dinv[node];
    const float4* hp = (const float4*)g_bufA;
    float4 hd = __ldg(&hp[(size_t)node * 8 + l8]);
    float4 acc = make_float4(hd.x * dv, hd.y * dv, hd.z * dv, hd.w * dv);

    int beg = g_rowptr[node], end = g_rowptr[node + 1];
    for (int e = beg; e < end; e++) {
        int s = g_csr_src[e];
        float ds = __ldg(&g_dinv[s]);
        float4 v = __ldg(&hp[(size_t)s * 8 + l8]);
        acc.x += ds * v.x;
        acc.y += ds * v.y;
        acc.z += ds * v.z;
        acc.w += ds * v.w;
    }
    float4 b = __ldg(&((const float4*)bias)[l8]);
    acc.x = fmaxf(acc.x * dv + b.x, 0.0f);
    acc.y = fmaxf(acc.y * dv + b.y, 0.0f);
    acc.z = fmaxf(acc.z * dv + b.z, 0.0f);
    acc.w = fmaxf(acc.w * dv + b.w, 0.0f);

    int g = batch[node];
    float* sp = &g_sums[g * HID + l8 * 4];
    atomicAdd(sp + 0, acc.x);
    atomicAdd(sp + 1, acc.y);
    atomicAdd(sp + 2, acc.z);
    atomicAdd(sp + 3, acc.w);
    if (l8 == 0) atomicAdd(&g_cnt[g], 1);
}

// ---------------- final: out[g] = (sums[g]/max(cnt,1)) @ Wl + bl ----------------
__global__ void k_final(const float* __restrict__ Wl, const float* __restrict__ bl,
                        float* __restrict__ out, int n_graphs) {
    int g = blockIdx.x * blockDim.x + threadIdx.x;
    if (g >= n_graphs) return;
    float c = (float)g_cnt[g];
    float inv = 1.0f / fmaxf(c, 1.0f);
    float o0 = bl[0], o1 = bl[1];
#pragma unroll
    for (int j = 0; j < HID; j++) {
        float p = g_sums[g * HID + j] * inv;
        o0 += p * Wl[j * 2 + 0];
        o1 += p * Wl[j * 2 + 1];
    }
    out[g * 2 + 0] = o0;
    out[g * 2 + 1] = o1;
}

// ---------------- launch (kernel launches ONLY; no other CUDA API calls) ---------
extern "C" void kernel_launch(void* const* d_in, const int* in_sizes, int n_in,
                              void* d_out, int out_size) {
    const float* x     = (const float*)d_in[0];
    const int*   ei    = (const int*)d_in[1];
    const int*   batch = (const int*)d_in[2];
    const float* W1    = (const float*)d_in[3];
    const float* b1    = (const float*)d_in[4];
    const float* W2    = (const float*)d_in[5];
    const float* b2    = (const float*)d_in[6];
    const float* Wl    = (const float*)d_in[7];
    const float* bl    = (const float*)d_in[8];
    float*       out   = (float*)d_out;

    int n_nodes  = in_sizes[2];
    int n_edges  = in_sizes[1] / 2;
    int n_graphs = out_size / 2;

    // CSR build (reused by both layers)
    k_zero<<<256, 256>>>(n_nodes, n_graphs);
    k_deg<<<2048, 256>>>(ei, n_edges);
    k_scan<<<1, 1024>>>(n_nodes);
    k_fill<<<2048, 256>>>(ei, n_edges);

    // Layer 1: h1 = relu(GCN(x, W1, b1));  gemm: x -> g_bufA, pull: g_bufA -> g_bufB
    k_gemm<128, true><<<(n_nodes + 127) / 128, 128>>>(x, W1, n_nodes);
    k_pull<<<(n_nodes * 8 + 255) / 256, 256>>>(b1, n_nodes);

    // Layer 2: gemm: g_bufB -> g_bufA, pull+pool: g_bufA -> g_sums
    k_gemm<32, false><<<(n_nodes + 127) / 128, 128>>>(nullptr, W2, n_nodes);
    k_pull_pool<<<(n_nodes * 8 + 255) / 256, 256>>>(b2, batch, n_nodes);

    // Head
    k_final<<<(n_graphs + 255) / 256, 256>>>(Wl, bl, out, n_graphs);
}

// round 4
// speedup vs baseline: 1.0097x; 1.0097x over previous
#include <cuda_runtime.h>

#define HID 32

static const int MAXN = 100000;
static const int MAXE = 3200000;
static const int MAXG = 512;

// ---------------- device scratch (no allocations; referenced only by symbol) ----
__device__ int   g_deg[MAXN];
__device__ int   g_rowptr[MAXN + 1];
__device__ int   g_cursor[MAXN];
__device__ float g_dinv[MAXN];
__device__ int   g_csr_src[MAXE];
__device__ __align__(16) float g_bufA[(size_t)MAXN * HID];
__device__ __align__(16) float g_bufB[(size_t)MAXN * HID];
__device__ __align__(16) float g_sums[MAXG * HID];
__device__ int   g_cnt[MAXG];

// ---------------- zero scratch that must start at 0 each call ----------------
__global__ void k_zero(int n_nodes, int n_graphs) {
    int i = blockIdx.x * blockDim.x + threadIdx.x;
    int stride = gridDim.x * blockDim.x;
    for (int k = i; k < n_nodes; k += stride) g_deg[k] = 0;
    for (int k = i; k < n_graphs * HID; k += stride) g_sums[k] = 0.0f;
    for (int k = i; k < n_graphs; k += stride) g_cnt[k] = 0;
}

// ---------------- degree histogram over dst (int4-vectorized) ----------------
__global__ void k_deg(const int* __restrict__ ei, int n_edges) {
    int i = blockIdx.x * blockDim.x + threadIdx.x;
    int stride = gridDim.x * blockDim.x;
    int n4 = n_edges >> 2;
    const int4* dst4 = (const int4*)(ei + n_edges);   // dst row; 16B-aligned (n_edges mult of 4)
    for (int e = i; e < n4; e += stride) {
        int4 d = __ldg(&dst4[e]);
        atomicAdd(&g_deg[d.x], 1);
        atomicAdd(&g_deg[d.y], 1);
        atomicAdd(&g_deg[d.z], 1);
        atomicAdd(&g_deg[d.w], 1);
    }
    // tail
    for (int e = (n4 << 2) + i; e < n_edges; e += stride) {
        atomicAdd(&g_deg[ei[n_edges + e]], 1);
    }
}

// ---------------- single-block exclusive scan -> rowptr, cursor, dinv ----------------
__global__ void k_scan(int n) {
    __shared__ int part[1024];
    int t = threadIdx.x;
    int chunk = (n + 1023) >> 10;
    int beg = min(t * chunk, n);
    int end = min(beg + chunk, n);
    int s = 0;
    for (int i = beg; i < end; i++) s += g_deg[i];
    part[t] = s;
    __syncthreads();
    for (int off = 1; off < 1024; off <<= 1) {
        int v = (t >= off) ? part[t - off] : 0;
        __syncthreads();
        part[t] += v;
        __syncthreads();
    }
    int run = (t == 0) ? 0 : part[t - 1];
    for (int i = beg; i < end; i++) {
        g_rowptr[i] = run;
        g_cursor[i] = run;
        g_dinv[i] = rsqrtf((float)g_deg[i] + 1.0f);
        run += g_deg[i];
    }
    if (t == 1023) g_rowptr[n] = part[1023];
}

// ---------------- CSR fill: csr_src grouped by dst (int4-vectorized) ----------------
__global__ void k_fill(const int* __restrict__ ei, int n_edges) {
    int i = blockIdx.x * blockDim.x + threadIdx.x;
    int stride = gridDim.x * blockDim.x;
    int n4 = n_edges >> 2;
    const int4* src4 = (const int4*)ei;
    const int4* dst4 = (const int4*)(ei + n_edges);
    for (int e = i; e < n4; e += stride) {
        int4 s = __ldg(&src4[e]);
        int4 d = __ldg(&dst4[e]);
        g_csr_src[atomicAdd(&g_cursor[d.x], 1)] = s.x;
        g_csr_src[atomicAdd(&g_cursor[d.y], 1)] = s.y;
        g_csr_src[atomicAdd(&g_cursor[d.z], 1)] = s.z;
        g_csr_src[atomicAdd(&g_cursor[d.w], 1)] = s.w;
    }
    for (int e = (n4 << 2) + i; e < n_edges; e += stride) {
        int s = ei[e];
        int d = ei[n_edges + e];
        g_csr_src[atomicAdd(&g_cursor[d], 1)] = s;
    }
}

// ---------------- dense GEMM: Y[n,32] = (X[n,K] @ W[K,32]) * dinv[n] -------------
// IN_EXT: read X from the external pointer; otherwise read g_bufB.
// Output (pre-scaled by dinv) always goes to g_bufA.
template <int K, bool IN_EXT>
__global__ void k_gemm(const float* __restrict__ Xext, const float* __restrict__ W,
                       int n) {
    __shared__ float Ws[K * HID];
    for (int i = threadIdx.x; i < K * HID; i += blockDim.x) Ws[i] = W[i];
    __syncthreads();

    int node = blockIdx.x * blockDim.x + threadIdx.x;
    if (node >= n) return;

    const float* X = IN_EXT ? Xext : (const float*)g_bufB;

    float4 acc[8];
#pragma unroll
    for (int j = 0; j < 8; j++) acc[j] = make_float4(0.f, 0.f, 0.f, 0.f);

    const float4* xp = (const float4*)(X + (size_t)node * K);
#pragma unroll 4
    for (int k4 = 0; k4 < K / 4; k4++) {
        float4 xv = __ldg(xp + k4);
        float xs[4] = {xv.x, xv.y, xv.z, xv.w};
#pragma unroll
        for (int kk = 0; kk < 4; kk++) {
            float xk = xs[kk];
            const float4* wr = (const float4*)&Ws[(k4 * 4 + kk) * HID];
#pragma unroll
            for (int j = 0; j < 8; j++) {
                float4 w = wr[j];
                acc[j].x += xk * w.x;
                acc[j].y += xk * w.y;
                acc[j].z += xk * w.z;
                acc[j].w += xk * w.w;
            }
        }
    }
    float dv = g_dinv[node];
    float4* yp = (float4*)(g_bufA + (size_t)node * HID);
#pragma unroll
    for (int j = 0; j < 8; j++) {
        acc[j].x *= dv; acc[j].y *= dv; acc[j].z *= dv; acc[j].w *= dv;
        yp[j] = acc[j];
    }
}

// ---------------- pull aggregation core --------------------------------------
// Input rows in g_bufA are pre-scaled: p[i] = (X@W)[i] * dinv[i].
// out = relu( dv * (sum_{s in N(d)} p_s + p_d) + b )
// 8 threads per node; each owns one float4 column slot. Edge loop unrolled x4
// for memory-level parallelism (4 independent index loads -> 4 gathers).
__device__ __forceinline__ float4 pull_acc(int node, int l8) {
    const float4* hp = (const float4*)g_bufA;
    float4 acc = __ldg(&hp[(size_t)node * 8 + l8]);   // self term (pre-scaled)

    int e = g_rowptr[node], end = g_rowptr[node + 1];
    for (; e + 4 <= end; e += 4) {
        int s0 = __ldg(&g_csr_src[e + 0]);
        int s1 = __ldg(&g_csr_src[e + 1]);
        int s2 = __ldg(&g_csr_src[e + 2]);
        int s3 = __ldg(&g_csr_src[e + 3]);
        float4 v0 = __ldg(&hp[(size_t)s0 * 8 + l8]);
        float4 v1 = __ldg(&hp[(size_t)s1 * 8 + l8]);
        float4 v2 = __ldg(&hp[(size_t)s2 * 8 + l8]);
        float4 v3 = __ldg(&hp[(size_t)s3 * 8 + l8]);
        acc.x += (v0.x + v1.x) + (v2.x + v3.x);
        acc.y += (v0.y + v1.y) + (v2.y + v3.y);
        acc.z += (v0.z + v1.z) + (v2.z + v3.z);
        acc.w += (v0.w + v1.w) + (v2.w + v3.w);
    }
    for (; e < end; e++) {
        int s = __ldg(&g_csr_src[e]);
        float4 v = __ldg(&hp[(size_t)s * 8 + l8]);
        acc.x += v.x; acc.y += v.y; acc.z += v.z; acc.w += v.w;
    }
    return acc;
}

// Reads g_bufA (pre-scaled), writes g_bufB (unscaled relu output).
__global__ void k_pull(const float* __restrict__ bias, int n) {
    int gid = blockIdx.x * blockDim.x + threadIdx.x;
    int node = gid >> 3;
    int l8 = gid & 7;
    if (node >= n) return;

    float4 acc = pull_acc(node, l8);
    float dv = g_dinv[node];
    float4 b = __ldg(&((const float4*)bias)[l8]);
    acc.x = fmaxf(fmaf(acc.x, dv, b.x), 0.0f);
    acc.y = fmaxf(fmaf(acc.y, dv, b.y), 0.0f);
    acc.z = fmaxf(fmaf(acc.z, dv, b.z), 0.0f);
    acc.w = fmaxf(fmaf(acc.w, dv, b.w), 0.0f);
    ((float4*)g_bufB)[(size_t)node * 8 + l8] = acc;
}

// Same, but accumulates into per-graph sums instead of writing rows.
__global__ void k_pull_pool(const float* __restrict__ bias,
                            const int* __restrict__ batch, int n) {
    int gid = blockIdx.x * blockDim.x + threadIdx.x;
    int node = gid >> 3;
    int l8 = gid & 7;
    if (node >= n) return;

    float4 acc = pull_acc(node, l8);
    float dv = g_dinv[node];
    float4 b = __ldg(&((const float4*)bias)[l8]);
    acc.x = fmaxf(fmaf(acc.x, dv, b.x), 0.0f);
    acc.y = fmaxf(fmaf(acc.y, dv, b.y), 0.0f);
    acc.z = fmaxf(fmaf(acc.z, dv, b.z), 0.0f);
    acc.w = fmaxf(fmaf(acc.w, dv, b.w), 0.0f);

    int g = batch[node];
    float* sp = &g_sums[g * HID + l8 * 4];
    atomicAdd(sp + 0, acc.x);
    atomicAdd(sp + 1, acc.y);
    atomicAdd(sp + 2, acc.z);
    atomicAdd(sp + 3, acc.w);
    if (l8 == 0) atomicAdd(&g_cnt[g], 1);
}

// ---------------- final: out[g] = (sums[g]/max(cnt,1)) @ Wl + bl ----------------
__global__ void k_final(const float* __restrict__ Wl, const float* __restrict__ bl,
                        float* __restrict__ out, int n_graphs) {
    int g = blockIdx.x * blockDim.x + threadIdx.x;
    if (g >= n_graphs) return;
    float c = (float)g_cnt[g];
    float inv = 1.0f / fmaxf(c, 1.0f);
    float o0 = bl[0], o1 = bl[1];
#pragma unroll
    for (int j = 0; j < HID; j++) {
        float p = g_sums[g * HID + j] * inv;
        o0 += p * Wl[j * 2 + 0];
        o1 += p * Wl[j * 2 + 1];
    }
    out[g * 2 + 0] = o0;
    out[g * 2 + 1] = o1;
}

// ---------------- launch (kernel launches ONLY) ---------------------------------
extern "C" void kernel_launch(void* const* d_in, const int* in_sizes, int n_in,
                              void* d_out, int out_size) {
    const float* x     = (const float*)d_in[0];
    const int*   ei    = (const int*)d_in[1];
    const int*   batch = (const int*)d_in[2];
    const float* W1    = (const float*)d_in[3];
    const float* b1    = (const float*)d_in[4];
    const float* W2    = (const float*)d_in[5];
    const float* b2    = (const float*)d_in[6];
    const float* Wl    = (const float*)d_in[7];
    const float* bl    = (const float*)d_in[8];
    float*       out   = (float*)d_out;

    int n_nodes  = in_sizes[2];
    int n_edges  = in_sizes[1] / 2;
    int n_graphs = out_size / 2;

    // CSR build (reused by both layers)
    k_zero<<<256, 256>>>(n_nodes, n_graphs);
    k_deg<<<1024, 256>>>(ei, n_edges);
    k_scan<<<1, 1024>>>(n_nodes);
    k_fill<<<1024, 256>>>(ei, n_edges);

    // Layer 1: gemm (pre-scaled by dinv): x -> g_bufA; pull: g_bufA -> g_bufB
    k_gemm<128, true><<<(n_nodes + 127) / 128, 128>>>(x, W1, n_nodes);
    k_pull<<<(n_nodes * 8 + 255) / 256, 256>>>(b1, n_nodes);

    // Layer 2: gemm (pre-scaled): g_bufB -> g_bufA; pull+pool: g_bufA -> g_sums
    k_gemm<32, false><<<(n_nodes + 127) / 128, 128>>>(nullptr, W2, n_nodes);
    k_pull_pool<<<(n_nodes * 8 + 255) / 256, 256>>>(b2, batch, n_nodes);

    // Head
    k_final<<<(n_graphs + 255) / 256, 256>>>(Wl, bl, out, n_graphs);
}

// round 5
// speedup vs baseline: 1.0311x; 1.0211x over previous
#include <cuda_runtime.h>

#define HID 32

static const int MAXN = 100000;
static const int MAXE = 3200000;
static const int MAXG = 512;

// ---------------- device scratch (no allocations; referenced only by symbol) ----
__device__ int   g_deg[MAXN];
__device__ int   g_rowptr[MAXN + 1];
__device__ int   g_cursor[MAXN];
__device__ float g_dinv[MAXN];
__device__ int   g_csr_src[MAXE];
__device__ __align__(16) float g_bufA[(size_t)MAXN * HID];  // layer-1 prescaled feats
__device__ __align__(16) float g_bufB[(size_t)MAXN * HID];  // layer-2 prescaled feats
__device__ __align__(16) float g_sums[MAXG * HID];
__device__ int   g_cnt[MAXG];

// ---------------- zero scratch that must start at 0 each call ----------------
__global__ void k_zero(int n_nodes, int n_graphs) {
    int i = blockIdx.x * blockDim.x + threadIdx.x;
    int stride = gridDim.x * blockDim.x;
    for (int k = i; k < n_nodes; k += stride) g_deg[k] = 0;
    for (int k = i; k < n_graphs * HID; k += stride) g_sums[k] = 0.0f;
    for (int k = i; k < n_graphs; k += stride) g_cnt[k] = 0;
}

// ================= fused: degree histogram (atomics) || gemm1 (x@W1 -> bufA) =====
// The two roles touch disjoint state, so they run concurrently in one grid.
// Deg blocks come first so the longer-running role is scheduled first.
static const int DEG_BLOCKS = 512;

__global__ void k_deg_gemm1(const int* __restrict__ ei, int n_edges,
                            const float* __restrict__ x, const float* __restrict__ W1,
                            int n_nodes) {
    __shared__ float Ws[128 * HID];   // 16 KB, used by gemm role only

    if (blockIdx.x < DEG_BLOCKS) {
        // ---- degree histogram over dst (int4-vectorized) ----
        int i = blockIdx.x * blockDim.x + threadIdx.x;
        int stride = DEG_BLOCKS * blockDim.x;
        int n4 = n_edges >> 2;
        const int4* dst4 = (const int4*)(ei + n_edges);
        for (int e = i; e < n4; e += stride) {
            int4 d = __ldg(&dst4[e]);
            atomicAdd(&g_deg[d.x], 1);
            atomicAdd(&g_deg[d.y], 1);
            atomicAdd(&g_deg[d.z], 1);
            atomicAdd(&g_deg[d.w], 1);
        }
        for (int e = (n4 << 2) + i; e < n_edges; e += stride) {
            atomicAdd(&g_deg[ei[n_edges + e]], 1);
        }
    } else {
        // ---- gemm1: bufA[node] = x[node] @ W1 (unscaled; dinv applied later) ----
        for (int i = threadIdx.x; i < 128 * HID; i += blockDim.x) Ws[i] = W1[i];
        __syncthreads();

        int node = (blockIdx.x - DEG_BLOCKS) * blockDim.x + threadIdx.x;
        if (node >= n_nodes) return;

        float4 acc[8];
#pragma unroll
        for (int j = 0; j < 8; j++) acc[j] = make_float4(0.f, 0.f, 0.f, 0.f);

        const float4* xp = (const float4*)(x + (size_t)node * 128);
#pragma unroll 4
        for (int k4 = 0; k4 < 32; k4++) {
            float4 xv = __ldg(xp + k4);
            float xs[4] = {xv.x, xv.y, xv.z, xv.w};
#pragma unroll
            for (int kk = 0; kk < 4; kk++) {
                float xk = xs[kk];
                const float4* wr = (const float4*)&Ws[(k4 * 4 + kk) * HID];
#pragma unroll
                for (int j = 0; j < 8; j++) {
                    float4 w = wr[j];
                    acc[j].x += xk * w.x;
                    acc[j].y += xk * w.y;
                    acc[j].z += xk * w.z;
                    acc[j].w += xk * w.w;
                }
            }
        }
        float4* yp = (float4*)(g_bufA + (size_t)node * HID);
#pragma unroll
        for (int j = 0; j < 8; j++) yp[j] = acc[j];
    }
}

// ---------------- single-block exclusive scan -> rowptr, cursor, dinv ----------------
__global__ void k_scan(int n) {
    __shared__ int part[1024];
    int t = threadIdx.x;
    int chunk = (n + 1023) >> 10;
    int beg = min(t * chunk, n);
    int end = min(beg + chunk, n);
    int s = 0;
    for (int i = beg; i < end; i++) s += g_deg[i];
    part[t] = s;
    __syncthreads();
    for (int off = 1; off < 1024; off <<= 1) {
        int v = (t >= off) ? part[t - off] : 0;
        __syncthreads();
        part[t] += v;
        __syncthreads();
    }
    int run = (t == 0) ? 0 : part[t - 1];
    for (int i = beg; i < end; i++) {
        g_rowptr[i] = run;
        g_cursor[i] = run;
        g_dinv[i] = rsqrtf((float)g_deg[i] + 1.0f);
        run += g_deg[i];
    }
    if (t == 1023) g_rowptr[n] = part[1023];
}

// ================= fused: CSR fill (atomics) || bufA *= dinv prescale ==========
static const int FILL_BLOCKS = 512;

__global__ void k_fill_scale(const int* __restrict__ ei, int n_edges, int n_nodes) {
    if (blockIdx.x < FILL_BLOCKS) {
        // ---- CSR fill ----
        int i = blockIdx.x * blockDim.x + threadIdx.x;
        int stride = FILL_BLOCKS * blockDim.x;
        int n4 = n_edges >> 2;
        const int4* src4 = (const int4*)ei;
        const int4* dst4 = (const int4*)(ei + n_edges);
        for (int e = i; e < n4; e += stride) {
            int4 s = __ldg(&src4[e]);
            int4 d = __ldg(&dst4[e]);
            g_csr_src[atomicAdd(&g_cursor[d.x], 1)] = s.x;
            g_csr_src[atomicAdd(&g_cursor[d.y], 1)] = s.y;
            g_csr_src[atomicAdd(&g_cursor[d.z], 1)] = s.z;
            g_csr_src[atomicAdd(&g_cursor[d.w], 1)] = s.w;
        }
        for (int e = (n4 << 2) + i; e < n_edges; e += stride) {
            int s = ei[e];
            int d = ei[n_edges + e];
            g_csr_src[atomicAdd(&g_cursor[d], 1)] = s;
        }
    } else {
        // ---- prescale bufA rows by dinv (one float4 per thread) ----
        int gid = (blockIdx.x - FILL_BLOCKS) * blockDim.x + threadIdx.x;
        int total = n_nodes * 8;
        if (gid >= total) return;
        float dv = g_dinv[gid >> 3];
        float4* p = (float4*)g_bufA + gid;
        float4 v = *p;
        v.x *= dv; v.y *= dv; v.z *= dv; v.w *= dv;
        *p = v;
    }
}

// ---------------- pull aggregation core (unroll x8 for MLP) -------------------
// Input rows are pre-scaled: p[i] = feats[i] * dinv[i].
// Returns sum_{s in N(d)} p_s + p_d (self term included).
template <bool SRC_A>
__device__ __forceinline__ float4 pull_acc(int node, int l8) {
    const float4* hp = SRC_A ? (const float4*)g_bufA : (const float4*)g_bufB;
    float4 acc = __ldg(&hp[(size_t)node * 8 + l8]);

    int e = g_rowptr[node], end = g_rowptr[node + 1];
    for (; e + 8 <= end; e += 8) {
        int s0 = __ldg(&g_csr_src[e + 0]);
        int s1 = __ldg(&g_csr_src[e + 1]);
        int s2 = __ldg(&g_csr_src[e + 2]);
        int s3 = __ldg(&g_csr_src[e + 3]);
        int s4 = __ldg(&g_csr_src[e + 4]);
        int s5 = __ldg(&g_csr_src[e + 5]);
        int s6 = __ldg(&g_csr_src[e + 6]);
        int s7 = __ldg(&g_csr_src[e + 7]);
        float4 v0 = __ldg(&hp[(size_t)s0 * 8 + l8]);
        float4 v1 = __ldg(&hp[(size_t)s1 * 8 + l8]);
        float4 v2 = __ldg(&hp[(size_t)s2 * 8 + l8]);
        float4 v3 = __ldg(&hp[(size_t)s3 * 8 + l8]);
        float4 v4 = __ldg(&hp[(size_t)s4 * 8 + l8]);
        float4 v5 = __ldg(&hp[(size_t)s5 * 8 + l8]);
        float4 v6 = __ldg(&hp[(size_t)s6 * 8 + l8]);
        float4 v7 = __ldg(&hp[(size_t)s7 * 8 + l8]);
        acc.x += ((v0.x + v1.x) + (v2.x + v3.x)) + ((v4.x + v5.x) + (v6.x + v7.x));
        acc.y += ((v0.y + v1.y) + (v2.y + v3.y)) + ((v4.y + v5.y) + (v6.y + v7.y));
        acc.z += ((v0.z + v1.z) + (v2.z + v3.z)) + ((v4.z + v5.z) + (v6.z + v7.z));
        acc.w += ((v0.w + v1.w) + (v2.w + v3.w)) + ((v4.w + v5.w) + (v6.w + v7.w));
    }
    for (; e < end; e++) {
        int s = __ldg(&g_csr_src[e]);
        float4 v = __ldg(&hp[(size_t)s * 8 + l8]);
        acc.x += v.x; acc.y += v.y; acc.z += v.z; acc.w += v.w;
    }
    return acc;
}

// ================= fused: pull layer 1 + relu + gemm2 + prescale ===============
// Reads g_bufA (prescaled layer-1 feats), writes g_bufB (prescaled layer-2 feats):
//   h1   = relu(dv * pull_acc + b1)          [exchanged via smem]
//   bufB = (h1 @ W2) * dv
// 256 threads = 32 nodes/block, 8 threads (one float4 slot) per node.
__global__ void k_pull_gemm2(const float* __restrict__ bias,
                             const float* __restrict__ W2, int n) {
    __shared__ float h_s[32 * HID];   // 4 KB
    __shared__ float W2s[HID * HID];  // 4 KB
    for (int i = threadIdx.x; i < HID * HID; i += blockDim.x) W2s[i] = W2[i];

    int tid = threadIdx.x;
    int nl = tid >> 3;          // node-local 0..31
    int l8 = tid & 7;           // float4 slot
    int node = blockIdx.x * 32 + nl;
    bool valid = node < n;

    if (valid) {
        float4 acc = pull_acc<true>(node, l8);
        float dv = g_dinv[node];
        float4 b = __ldg(&((const float4*)bias)[l8]);
        acc.x = fmaxf(fmaf(acc.x, dv, b.x), 0.0f);
        acc.y = fmaxf(fmaf(acc.y, dv, b.y), 0.0f);
        acc.z = fmaxf(fmaf(acc.z, dv, b.z), 0.0f);
        acc.w = fmaxf(fmaf(acc.w, dv, b.w), 0.0f);
        ((float4*)&h_s[nl * HID])[l8] = acc;
    }
    __syncthreads();
    if (!valid) return;

    // gemm2: 4 output columns per thread
    float4 o = make_float4(0.f, 0.f, 0.f, 0.f);
    const float* hr = &h_s[nl * HID];
    const float4* w4 = (const float4*)W2s;
#pragma unroll
    for (int k = 0; k < HID; k++) {
        float hk = hr[k];
        float4 w = w4[k * 8 + l8];
        o.x = fmaf(hk, w.x, o.x);
        o.y = fmaf(hk, w.y, o.y);
        o.z = fmaf(hk, w.z, o.z);
        o.w = fmaf(hk, w.w, o.w);
    }
    float dv = g_dinv[node];
    o.x *= dv; o.y *= dv; o.z *= dv; o.w *= dv;
    ((float4*)g_bufB)[(size_t)node * 8 + l8] = o;
}

// ---------------- pull layer 2 + fused mean-pool accumulation (reads g_bufB) ----
__global__ void k_pull_pool(const float* __restrict__ bias,
                            const int* __restrict__ batch, int n) {
    int gid = blockIdx.x * blockDim.x + threadIdx.x;
    int node = gid >> 3;
    int l8 = gid & 7;
    if (node >= n) return;

    float4 acc = pull_acc<false>(node, l8);
    float dv = g_dinv[node];
    float4 b = __ldg(&((const float4*)bias)[l8]);
    acc.x = fmaxf(fmaf(acc.x, dv, b.x), 0.0f);
    acc.y = fmaxf(fmaf(acc.y, dv, b.y), 0.0f);
    acc.z = fmaxf(fmaf(acc.z, dv, b.z), 0.0f);
    acc.w = fmaxf(fmaf(acc.w, dv, b.w), 0.0f);

    int g = batch[node];
    float* sp = &g_sums[g * HID + l8 * 4];
    atomicAdd(sp + 0, acc.x);
    atomicAdd(sp + 1, acc.y);
    atomicAdd(sp + 2, acc.z);
    atomicAdd(sp + 3, acc.w);
    if (l8 == 0) atomicAdd(&g_cnt[g], 1);
}

// ---------------- final: out[g] = (sums[g]/max(cnt,1)) @ Wl + bl ----------------
__global__ void k_final(const float* __restrict__ Wl, const float* __restrict__ bl,
                        float* __restrict__ out, int n_graphs) {
    int g = blockIdx.x * blockDim.x + threadIdx.x;
    if (g >= n_graphs) return;
    float c = (float)g_cnt[g];
    float inv = 1.0f / fmaxf(c, 1.0f);
    float o0 = bl[0], o1 = bl[1];
#pragma unroll
    for (int j = 0; j < HID; j++) {
        float p = g_sums[g * HID + j] * inv;
        o0 += p * Wl[j * 2 + 0];
        o1 += p * Wl[j * 2 + 1];
    }
    out[g * 2 + 0] = o0;
    out[g * 2 + 1] = o1;
}

// ---------------- launch (kernel launches ONLY) ---------------------------------
extern "C" void kernel_launch(void* const* d_in, const int* in_sizes, int n_in,
                              void* d_out, int out_size) {
    const float* x     = (const float*)d_in[0];
    const int*   ei    = (const int*)d_in[1];
    const int*   batch = (const int*)d_in[2];
    const float* W1    = (const float*)d_in[3];
    const float* b1    = (const float*)d_in[4];
    const float* W2    = (const float*)d_in[5];
    const float* b2    = (const float*)d_in[6];
    const float* Wl    = (const float*)d_in[7];
    const float* bl    = (const float*)d_in[8];
    float*       out   = (float*)d_out;

    int n_nodes  = in_sizes[2];
    int n_edges  = in_sizes[1] / 2;
    int n_graphs = out_size / 2;

    // 1) zero counters/sums
    k_zero<<<256, 256>>>(n_nodes, n_graphs);

    // 2) degree histogram || gemm1 (concurrent roles in one grid)
    int gemm_blocks = (n_nodes + 255) / 256;
    k_deg_gemm1<<<DEG_BLOCKS + gemm_blocks, 256>>>(ei, n_edges, x, W1, n_nodes);

    // 3) scan -> rowptr/cursor/dinv
    k_scan<<<1, 1024>>>(n_nodes);

    // 4) CSR fill || bufA *= dinv
    int scale_blocks = (n_nodes * 8 + 255) / 256;
    k_fill_scale<<<FILL_BLOCKS + scale_blocks, 256>>>(ei, n_edges, n_nodes);

    // 5) pull layer 1 + relu + gemm2 + prescale -> bufB
    k_pull_gemm2<<<(n_nodes + 31) / 32, 256>>>(b1, W2, n_nodes);

    // 6) pull layer 2 + relu + mean-pool accumulate
    k_pull_pool<<<(n_nodes * 8 + 255) / 256, 256>>>(b2, batch, n_nodes);

    // 7) head
    k_final<<<(n_graphs + 255) / 256, 256>>>(Wl, bl, out, n_graphs);
}

// round 6
// speedup vs baseline: 1.9897x; 1.9297x over previous
#include <cuda_runtime.h>
#include <cuda_fp16.h>

#define HID 32

static const int MAXN = 100000;
static const int MAXE = 3200000;
static const int MAXG = 512;
static const int MAXB = 1024;   // scan tile blocks bound

// ---------------- device scratch (no allocations; referenced only by symbol) ----
__device__ int   g_deg[MAXN + 4];
__device__ int   g_rowptr[MAXN + 1];
__device__ int   g_cursor[MAXN];
__device__ float g_dinv[MAXN];
__device__ int   g_csr_src[MAXE];
__device__ int   g_bsum[MAXB];
__device__ int   g_boff[MAXB];
__device__ __align__(16) float g_bufA[(size_t)MAXN * HID];  // gemm1 fp32 out
__device__ uint4 g_hA[(size_t)MAXN * 4];                    // layer-1 prescaled half feats
__device__ uint4 g_hB[(size_t)MAXN * 4];                    // layer-2 prescaled half feats
__device__ __align__(16) float g_sums[MAXG * HID];
__device__ int   g_cnt[MAXG];

// ---------------- half pack/unpack helpers ----------------
__device__ __forceinline__ unsigned pack2(float a, float b) {
    __half2 h = __floats2half2_rn(a, b);
    return *reinterpret_cast<unsigned*>(&h);
}
__device__ __forceinline__ float2 unpack2(unsigned u) {
    __half2 h = *reinterpret_cast<__half2*>(&u);
    return __half22float2(h);
}

// ---------------- zero scratch that must start at 0 each call ----------------
__global__ void k_zero(int n_nodes, int n_graphs) {
    int i = blockIdx.x * blockDim.x + threadIdx.x;
    int stride = gridDim.x * blockDim.x;
    for (int k = i; k < n_nodes; k += stride) g_deg[k] = 0;
    for (int k = i; k < n_graphs * HID; k += stride) g_sums[k] = 0.0f;
    for (int k = i; k < n_graphs; k += stride) g_cnt[k] = 0;
}

// ================= fused: degree histogram (atomics) || gemm1 (x@W1 -> bufA) =====
// Roles interleaved by block index so both start in wave 1.
__global__ void k_deg_gemm1(const int* __restrict__ ei, int n_edges,
                            const float* __restrict__ x, const float* __restrict__ W1,
                            int n_nodes, int deg_blocks, int gemm_blocks) {
    __shared__ float Ws[128 * HID];   // 16 KB, gemm role only

    int b = blockIdx.x;
    bool is_gemm;
    int rb;  // role-local block index
    if (b < 2 * gemm_blocks) { is_gemm = (b & 1); rb = b >> 1; }
    else                     { is_gemm = false;   rb = b - gemm_blocks; }

    if (!is_gemm) {
        // ---- degree histogram over dst (int4-vectorized) ----
        int i = rb * blockDim.x + threadIdx.x;
        int stride = deg_blocks * blockDim.x;
        int n4 = n_edges >> 2;
        const int4* dst4 = (const int4*)(ei + n_edges);
        for (int e = i; e < n4; e += stride) {
            int4 d = __ldg(&dst4[e]);
            atomicAdd(&g_deg[d.x], 1);
            atomicAdd(&g_deg[d.y], 1);
            atomicAdd(&g_deg[d.z], 1);
            atomicAdd(&g_deg[d.w], 1);
        }
        for (int e = (n4 << 2) + i; e < n_edges; e += stride) {
            atomicAdd(&g_deg[ei[n_edges + e]], 1);
        }
    } else {
        // ---- gemm1: bufA[node] = x[node] @ W1 (fp32; dinv not ready yet) ----
        for (int i = threadIdx.x; i < 128 * HID; i += blockDim.x) Ws[i] = W1[i];
        __syncthreads();

        int node = rb * blockDim.x + threadIdx.x;
        if (node >= n_nodes) return;

        float4 acc[8];
#pragma unroll
        for (int j = 0; j < 8; j++) acc[j] = make_float4(0.f, 0.f, 0.f, 0.f);

        const float4* xp = (const float4*)(x + (size_t)node * 128);
#pragma unroll 4
        for (int k4 = 0; k4 < 32; k4++) {
            float4 xv = __ldg(xp + k4);
            float xs[4] = {xv.x, xv.y, xv.z, xv.w};
#pragma unroll
            for (int kk = 0; kk < 4; kk++) {
                float xk = xs[kk];
                const float4* wr = (const float4*)&Ws[(k4 * 4 + kk) * HID];
#pragma unroll
                for (int j = 0; j < 8; j++) {
                    float4 w = wr[j];
                    acc[j].x += xk * w.x;
                    acc[j].y += xk * w.y;
                    acc[j].z += xk * w.z;
                    acc[j].w += xk * w.w;
                }
            }
        }
        float4* yp = (float4*)(g_bufA + (size_t)node * HID);
#pragma unroll
        for (int j = 0; j < 8; j++) yp[j] = acc[j];
    }
}

// ================= multi-block coalesced scan (3 launches) ======================
// Tile = 1024 elements per block (256 threads x int4).
__global__ void k_scan1(int n) {
    __shared__ int wsum[8];
    int i = blockIdx.x * 1024 + threadIdx.x * 4;
    int4 d = make_int4(0, 0, 0, 0);
    if (i + 3 < n) d = *(const int4*)&g_deg[i];
    else {
        if (i + 0 < n) d.x = g_deg[i + 0];
        if (i + 1 < n) d.y = g_deg[i + 1];
        if (i + 2 < n) d.z = g_deg[i + 2];
    }
    int s = d.x + d.y + d.z + d.w;
#pragma unroll
    for (int off = 16; off > 0; off >>= 1) s += __shfl_down_sync(0xffffffffu, s, off);
    if ((threadIdx.x & 31) == 0) wsum[threadIdx.x >> 5] = s;
    __syncthreads();
    if (threadIdx.x == 0) {
        int t = 0;
#pragma unroll
        for (int w = 0; w < 8; w++) t += wsum[w];
        g_bsum[blockIdx.x] = t;
    }
}

__global__ void k_scan2(int nb, int n) {
    __shared__ int sh[128];
    int t = threadIdx.x;
    int v = (t < nb) ? g_bsum[t] : 0;
    sh[t] = v;
    __syncthreads();
    for (int off = 1; off < 128; off <<= 1) {
        int u = (t >= off) ? sh[t - off] : 0;
        __syncthreads();
        sh[t] += u;
        __syncthreads();
    }
    if (t < nb) g_boff[t] = sh[t] - v;      // exclusive
    if (t == nb - 1) g_rowptr[n] = sh[t];   // total edges
}

__global__ void k_scan3(int n) {
    __shared__ int wsum[8];
    __shared__ int woff[8];
    int i = blockIdx.x * 1024 + threadIdx.x * 4;
    int4 d = make_int4(0, 0, 0, 0);
    if (i + 3 < n) d = *(const int4*)&g_deg[i];
    else {
        if (i + 0 < n) d.x = g_deg[i + 0];
        if (i + 1 < n) d.y = g_deg[i + 1];
        if (i + 2 < n) d.z = g_deg[i + 2];
    }
    int s = d.x + d.y + d.z + d.w;
    int lane = threadIdx.x & 31, wid = threadIdx.x >> 5;
    // warp inclusive scan
    int inc = s;
#pragma unroll
    for (int off = 1; off < 32; off <<= 1) {
        int u = __shfl_up_sync(0xffffffffu, inc, off);
        if (lane >= off) inc += u;
    }
    if (lane == 31) wsum[wid] = inc;
    __syncthreads();
    if (threadIdx.x == 0) {
        int r = 0;
#pragma unroll
        for (int w = 0; w < 8; w++) { woff[w] = r; r += wsum[w]; }
    }
    __syncthreads();
    int run = g_boff[blockIdx.x] + woff[wid] + (inc - s);  // exclusive for this thread
    if (i + 0 < n) { g_rowptr[i+0]=run; g_cursor[i+0]=run; g_dinv[i+0]=rsqrtf((float)d.x+1.f); run+=d.x; }
    if (i + 1 < n) { g_rowptr[i+1]=run; g_cursor[i+1]=run; g_dinv[i+1]=rsqrtf((float)d.y+1.f); run+=d.y; }
    if (i + 2 < n) { g_rowptr[i+2]=run; g_cursor[i+2]=run; g_dinv[i+2]=rsqrtf((float)d.z+1.f); run+=d.z; }
    if (i + 3 < n) { g_rowptr[i+3]=run; g_cursor[i+3]=run; g_dinv[i+3]=rsqrtf((float)d.w+1.f); run+=d.w; }
}

// ================= fused: CSR fill (atomics) || bufA -> half prescaled g_hA =====
__global__ void k_fill_cvt(const int* __restrict__ ei, int n_edges, int n_nodes,
                           int fill_blocks, int cvt_blocks) {
    int b = blockIdx.x;
    bool is_cvt;
    int rb;
    if (b < 2 * cvt_blocks) { is_cvt = (b & 1); rb = b >> 1; }
    else                    { is_cvt = false;   rb = b - cvt_blocks; }

    if (!is_cvt) {
        int i = rb * blockDim.x + threadIdx.x;
        int stride = fill_blocks * blockDim.x;
        int n4 = n_edges >> 2;
        const int4* src4 = (const int4*)ei;
        const int4* dst4 = (const int4*)(ei + n_edges);
        for (int e = i; e < n4; e += stride) {
            int4 s = __ldg(&src4[e]);
            int4 d = __ldg(&dst4[e]);
            g_csr_src[atomicAdd(&g_cursor[d.x], 1)] = s.x;
            g_csr_src[atomicAdd(&g_cursor[d.y], 1)] = s.y;
            g_csr_src[atomicAdd(&g_cursor[d.z], 1)] = s.z;
            g_csr_src[atomicAdd(&g_cursor[d.w], 1)] = s.w;
        }
        for (int e = (n4 << 2) + i; e < n_edges; e += stride) {
            int s = ei[e];
            int d = ei[n_edges + e];
            g_csr_src[atomicAdd(&g_cursor[d], 1)] = s;
        }
    } else {
        // convert 8 columns per thread: g_hA = half(bufA * dinv)
        int c = rb * blockDim.x + threadIdx.x;   // over n_nodes*4
        if (c >= n_nodes * 4) return;
        int node = c >> 2, l4 = c & 3;
        float dv = g_dinv[node];
        const float4* src = (const float4*)(g_bufA + (size_t)node * HID) + l4 * 2;
        float4 a = src[0], b2 = src[1];
        uint4 o;
        o.x = pack2(a.x * dv,  a.y * dv);
        o.y = pack2(a.z * dv,  a.w * dv);
        o.z = pack2(b2.x * dv, b2.y * dv);
        o.w = pack2(b2.z * dv, b2.w * dv);
        g_hA[(size_t)node * 4 + l4] = o;
    }
}

// ---------------- half pull aggregation core (4 threads/node, unroll x8) --------
// Rows are prescaled halves: p[i] = feats[i] * dinv[i]. Returns fp32
// acc[8] = sum_{s in N(d)} p_s + p_d for this thread's 8 columns.
template <bool SRC_A>
__device__ __forceinline__ void pull_acc_h(int node, int l4, float* acc) {
    const uint4* hp = SRC_A ? g_hA : g_hB;
    uint4 v = __ldg(&hp[(size_t)node * 4 + l4]);
    {
        float2 f0 = unpack2(v.x), f1 = unpack2(v.y), f2 = unpack2(v.z), f3 = unpack2(v.w);
        acc[0] = f0.x; acc[1] = f0.y; acc[2] = f1.x; acc[3] = f1.y;
        acc[4] = f2.x; acc[5] = f2.y; acc[6] = f3.x; acc[7] = f3.y;
    }
    int e = g_rowptr[node], end = g_rowptr[node + 1];
    for (; e + 8 <= end; e += 8) {
        int s0 = __ldg(&g_csr_src[e + 0]);
        int s1 = __ldg(&g_csr_src[e + 1]);
        int s2 = __ldg(&g_csr_src[e + 2]);
        int s3 = __ldg(&g_csr_src[e + 3]);
        int s4 = __ldg(&g_csr_src[e + 4]);
        int s5 = __ldg(&g_csr_src[e + 5]);
        int s6 = __ldg(&g_csr_src[e + 6]);
        int s7 = __ldg(&g_csr_src[e + 7]);
        uint4 w0 = __ldg(&hp[(size_t)s0 * 4 + l4]);
        uint4 w1 = __ldg(&hp[(size_t)s1 * 4 + l4]);
        uint4 w2 = __ldg(&hp[(size_t)s2 * 4 + l4]);
        uint4 w3 = __ldg(&hp[(size_t)s3 * 4 + l4]);
        uint4 w4 = __ldg(&hp[(size_t)s4 * 4 + l4]);
        uint4 w5 = __ldg(&hp[(size_t)s5 * 4 + l4]);
        uint4 w6 = __ldg(&hp[(size_t)s6 * 4 + l4]);
        uint4 w7 = __ldg(&hp[(size_t)s7 * 4 + l4]);
#pragma unroll
        for (int q = 0; q < 8; q++) {
            uint4 w = (q==0)?w0:(q==1)?w1:(q==2)?w2:(q==3)?w3:(q==4)?w4:(q==5)?w5:(q==6)?w6:w7;
            float2 f0 = unpack2(w.x), f1 = unpack2(w.y), f2 = unpack2(w.z), f3 = unpack2(w.w);
            acc[0] += f0.x; acc[1] += f0.y; acc[2] += f1.x; acc[3] += f1.y;
            acc[4] += f2.x; acc[5] += f2.y; acc[6] += f3.x; acc[7] += f3.y;
        }
    }
    for (; e < end; e++) {
        int s = __ldg(&g_csr_src[e]);
        uint4 w = __ldg(&hp[(size_t)s * 4 + l4]);
        float2 f0 = unpack2(w.x), f1 = unpack2(w.y), f2 = unpack2(w.z), f3 = unpack2(w.w);
        acc[0] += f0.x; acc[1] += f0.y; acc[2] += f1.x; acc[3] += f1.y;
        acc[4] += f2.x; acc[5] += f2.y; acc[6] += f3.x; acc[7] += f3.y;
    }
}

// ================= fused: pull layer 1 + relu + gemm2 + prescale -> g_hB =======
// 256 threads = 64 nodes/block, 4 threads (8 cols each) per node.
__global__ void k_pull_gemm2(const float* __restrict__ bias,
                             const float* __restrict__ W2, int n) {
    __shared__ float h_s[64 * HID];   // 8 KB
    __shared__ float W2s[HID * HID];  // 4 KB
    for (int i = threadIdx.x; i < HID * HID; i += blockDim.x) W2s[i] = W2[i];

    int tid = threadIdx.x;
    int nl = tid >> 2;          // node-local 0..63
    int l4 = tid & 3;           // 8-col slot
    int node = blockIdx.x * 64 + nl;
    bool valid = node < n;

    if (valid) {
        float acc[8];
        pull_acc_h<true>(node, l4, acc);
        float dv = g_dinv[node];
        float* hr = &h_s[nl * HID + l4 * 8];
#pragma unroll
        for (int j = 0; j < 8; j++) {
            float bj = __ldg(&bias[l4 * 8 + j]);
            hr[j] = fmaxf(fmaf(acc[j], dv, bj), 0.0f);
        }
    }
    __syncthreads();
    if (!valid) return;

    // gemm2: 8 output columns per thread
    float o[8];
#pragma unroll
    for (int j = 0; j < 8; j++) o[j] = 0.0f;
    const float* hr = &h_s[nl * HID];
#pragma unroll
    for (int k = 0; k < HID; k++) {
        float hk = hr[k];
        const float* wr = &W2s[k * HID + l4 * 8];
#pragma unroll
        for (int j = 0; j < 8; j++) o[j] = fmaf(hk, wr[j], o[j]);
    }
    float dv = g_dinv[node];
    uint4 ov;
    ov.x = pack2(o[0] * dv, o[1] * dv);
    ov.y = pack2(o[2] * dv, o[3] * dv);
    ov.z = pack2(o[4] * dv, o[5] * dv);
    ov.w = pack2(o[6] * dv, o[7] * dv);
    g_hB[(size_t)node * 4 + l4] = ov;
}

// ---------------- pull layer 2 + relu + mean-pool accumulate (reads g_hB) -------
__global__ void k_pull_pool(const float* __restrict__ bias,
                            const int* __restrict__ batch, int n) {
    int gid = blockIdx.x * blockDim.x + threadIdx.x;
    int node = gid >> 2;
    int l4 = gid & 3;
    if (node >= n) return;

    float acc[8];
    pull_acc_h<false>(node, l4, acc);
    float dv = g_dinv[node];
    int g = batch[node];
    float* sp = &g_sums[g * HID + l4 * 8];
#pragma unroll
    for (int j = 0; j < 8; j++) {
        float bj = __ldg(&bias[l4 * 8 + j]);
        float v = fmaxf(fmaf(acc[j], dv, bj), 0.0f);
        atomicAdd(sp + j, v);
    }
    if (l4 == 0) atomicAdd(&g_cnt[g], 1);
}

// ---------------- final: out[g] = (sums[g]/max(cnt,1)) @ Wl + bl ----------------
__global__ void k_final(const float* __restrict__ Wl, const float* __restrict__ bl,
                        float* __restrict__ out, int n_graphs) {
    int g = blockIdx.x * blockDim.x + threadIdx.x;
    if (g >= n_graphs) return;
    float c = (float)g_cnt[g];
    float inv = 1.0f / fmaxf(c, 1.0f);
    float o0 = bl[0], o1 = bl[1];
#pragma unroll
    for (int j = 0; j < HID; j++) {
        float p = g_sums[g * HID + j] * inv;
        o0 += p * Wl[j * 2 + 0];
        o1 += p * Wl[j * 2 + 1];
    }
    out[g * 2 + 0] = o0;
    out[g * 2 + 1] = o1;
}

// ---------------- launch (kernel launches ONLY) ---------------------------------
extern "C" void kernel_launch(void* const* d_in, const int* in_sizes, int n_in,
                              void* d_out, int out_size) {
    const float* x     = (const float*)d_in[0];
    const int*   ei    = (const int*)d_in[1];
    const int*   batch = (const int*)d_in[2];
    const float* W1    = (const float*)d_in[3];
    const float* b1    = (const float*)d_in[4];
    const float* W2    = (const float*)d_in[5];
    const float* b2    = (const float*)d_in[6];
    const float* Wl    = (const float*)d_in[7];
    const float* bl    = (const float*)d_in[8];
    float*       out   = (float*)d_out;

    int n_nodes  = in_sizes[2];
    int n_edges  = in_sizes[1] / 2;
    int n_graphs = out_size / 2;

    // 1) zero counters/sums
    k_zero<<<256, 256>>>(n_nodes, n_graphs);

    // 2) degree histogram || gemm1 (interleaved roles)
    int gemm_blocks = (n_nodes + 255) / 256;
    int deg_blocks  = 2048;
    k_deg_gemm1<<<deg_blocks + gemm_blocks, 256>>>(ei, n_edges, x, W1, n_nodes,
                                                   deg_blocks, gemm_blocks);

    // 3) coalesced multi-block scan -> rowptr/cursor/dinv
    int nb = (n_nodes + 1023) / 1024;
    k_scan1<<<nb, 256>>>(n_nodes);
    k_scan2<<<1, 128>>>(nb, n_nodes);
    k_scan3<<<nb, 256>>>(n_nodes);

    // 4) CSR fill || convert bufA -> prescaled half g_hA (interleaved roles)
    int cvt_blocks  = (n_nodes * 4 + 255) / 256;
    int fill_blocks = 2048;
    k_fill_cvt<<<fill_blocks + cvt_blocks, 256>>>(ei, n_edges, n_nodes,
                                                  fill_blocks, cvt_blocks);

    // 5) pull layer 1 + relu + gemm2 + prescale -> g_hB
    k_pull_gemm2<<<(n_nodes + 63) / 64, 256>>>(b1, W2, n_nodes);

    // 6) pull layer 2 + relu + mean-pool accumulate
    k_pull_pool<<<(n_nodes * 4 + 255) / 256, 256>>>(b2, batch, n_nodes);

    // 7) head
    k_final<<<(n_graphs + 255) / 256, 256>>>(Wl, bl, out, n_graphs);
}